// round 17
// baseline (speedup 1.0000x reference)
#include <cuda_runtime.h>
#include <cstdint>

// MC_Module_Batch: bilinear backward warp + weight + sum over R.
// 3-stage cp.async ring (1 barrier/iter), 32x8 tiles, 1 px/thread, 6 CTAs/SM,
// fully hoisted loader/gather/store address math.
// pred [B,R,C,H,W], mv [B,R,2,H,W] (quarter-pel), weight [B,R,1,H,W] -> out [B,C,H,W]

#define Bv 4
#define Rv 2
#define Cv 19
#define Hv 256
#define Wv 512
#define HW (Hv * Wv)

#define TILE_H 8
#define PADY 7
#define PADX 16
#define TROWS (TILE_H + 2 * PADY + 1)  // 23
#define TCOLS 64
#define TSZ   (TROWS * TCOLS)           // 1472 floats
#define TSZ4  (TSZ / 4)                 // 368 float4
#define NSTAGE 3
#define STAGE_BYTES (2 * TSZ * 4)
#define SMEM_BYTES (NSTAGE * STAGE_BYTES)   // 35328 B

__device__ __forceinline__ void cp_async16(uint32_t smem, const void* g) {
    asm volatile("cp.async.cg.shared.global [%0], [%1], 16;" :: "r"(smem), "l"(g));
}
__device__ __forceinline__ void cp_commit() {
    asm volatile("cp.async.commit_group;");
}
template<int N> __device__ __forceinline__ void cp_wait() {
    asm volatile("cp.async.wait_group %0;" :: "n"(N));
}

__global__ __launch_bounds__(256, 6)
void mc_warp_kernel(const float* __restrict__ pred,
                    const float* __restrict__ mv,
                    const float* __restrict__ wgt,
                    float* __restrict__ out)
{
    extern __shared__ __align__(16) float smem[];   // [NSTAGE][2 r][TSZ]
    const uint32_t smem_u32 = (uint32_t)__cvta_generic_to_shared(smem);

    const int tid = threadIdx.x;
    const int tx  = tid & 31;
    const int ty  = tid >> 5;            // 0..7
    const int bx  = blockIdx.x, by = blockIdx.y, b = blockIdx.z;
    const int x0blk = bx * 32;
    const int y0blk = by * TILE_H;
    const int x = x0blk + tx;
    const int y = y0blk + ty;
    const int wbase = min(max(x0blk - PADX, 0), Wv - TCOLS);
    const int rowbase = y0blk - PADY;

    // ---- Precompute taps (1 px/thread, 2 r) ----
    float w4[2][4];
    int   idesc[2];
    int   fall = 0;
    const int pix = y * Wv + x;
#pragma unroll
    for (int r = 0; r < Rv; ++r) {
        const int nr = b * Rv + r;
        const float mvx = __ldg(mv + (size_t)(nr * 2) * HW + pix) * 0.25f;
        const float mvy = __ldg(mv + (size_t)(nr * 2 + 1) * HW + pix) * 0.25f;
        const float w   = __ldg(wgt + (size_t)nr * HW + pix);

        const float gx = (float)x + mvx;
        const float gy = (float)y + mvy;
        const float x0f = floorf(gx), y0f = floorf(gy);
        const float wx1 = gx - x0f, wx0 = 1.0f - wx1;
        const float wy1 = gy - y0f, wy0 = 1.0f - wy1;

        const int x0 = (int)x0f, y0 = (int)y0f;
        const int x1 = x0 + 1,   y1 = y0 + 1;

        const float vx0 = ((unsigned)x0 < (unsigned)Wv) ? 1.0f : 0.0f;
        const float vx1 = ((unsigned)x1 < (unsigned)Wv) ? 1.0f : 0.0f;
        const float vy0 = ((unsigned)y0 < (unsigned)Hv) ? 1.0f : 0.0f;
        const float vy1 = ((unsigned)y1 < (unsigned)Hv) ? 1.0f : 0.0f;

        w4[r][0] = wy0 * wx0 * vy0 * vx0 * w;
        w4[r][1] = wy0 * wx1 * vy0 * vx1 * w;
        w4[r][2] = wy1 * wx0 * vy1 * vx0 * w;
        w4[r][3] = wy1 * wx1 * vy1 * vx1 * w;

        const int tT = y0 - rowbase;   // UNCLAMPED
        const int tX = x0 - wbase;     // UNCLAMPED
        if ((unsigned)tT <= (TROWS - 2) && (unsigned)tX <= (TCOLS - 2)) {
            idesc[r] = tT * TCOLS + tX;
        } else {
            const int cx0 = min(max(x0, 0), Wv - 1);
            const int cx1 = min(max(x1, 0), Wv - 1);
            const int cy0 = min(max(y0, 0), Hv - 1);
            const int cy1 = min(max(y1, 0), Hv - 1);
            idesc[r] = 0x40000000 | ((cy1 - cy0) << 21)
                     | ((cx1 - cx0) << 20) | (cy0 * Wv + cx0);
            fall = 1;
        }
    }
    const int anyfall = __syncthreads_or(fall);

    const float* pb0 = pred + (size_t)(b * Rv + 0) * Cv * HW;
    const float* pb1 = pred + (size_t)(b * Rv + 1) * Cv * HW;

    // ---- Hoisted loader addresses (loop-invariant) ----
    // Thread loads float4 index i0 = tid (always) and i1 = tid + 256 (tid < 112).
    const int wb4 = wbase >> 2;
    const int i0 = tid;
    const int i1 = tid + 256;
    const int gcy0 = min(max(rowbase + (i0 >> 4), 0), Hv - 1);
    const int gcy1 = min(max(rowbase + (i1 >> 4), 0), Hv - 1);
    const int g0 = gcy0 * (Wv / 4) + wb4 + (i0 & 15);   // float4 index in plane
    const int g1 = gcy1 * (Wv / 4) + wb4 + (i1 & 15);
    const uint32_t sm0 = smem_u32 + (uint32_t)i0 * 16u;
    const uint32_t sm1 = smem_u32 + (uint32_t)i1 * 16u;
    const bool has2 = (i1 < TSZ4);

    // Running source pointers (advance by HW per loaded channel).
    const float4* ld0 = (const float4*)pb0 + g0;            // r=0, i0
    const float4* ld1 = (const float4*)pb1 + g0;            // r=1, i0
    const float4* le0 = (const float4*)pb0 + g1;            // r=0, i1
    const float4* le1 = (const float4*)pb1 + g1;            // r=1, i1

    auto load_stage = [&](int st) {   // loads CURRENT ld*/le* channel into stage st
        const uint32_t off = (uint32_t)st * STAGE_BYTES;
        cp_async16(sm0 + off, ld0);
        cp_async16(sm0 + off + (uint32_t)TSZ * 4u, ld1);
        if (has2) {
            cp_async16(sm1 + off, le0);
            cp_async16(sm1 + off + (uint32_t)TSZ * 4u, le1);
        }
        ld0 += HW / 4; ld1 += HW / 4; le0 += HW / 4; le1 += HW / 4;
    };

    float* ob = out + (size_t)b * Cv * HW + pix;

    load_stage(0);
    cp_commit();
    load_stage(1);
    cp_commit();

    int st = 0;   // stage holding channel c
    int ld = 2;   // stage for channel c+2

    if (!anyfall) {
        const float* t0 = smem + idesc[0];           // stage-0 base for r=0 tap
        const float* t1 = smem + TSZ + idesc[1];     // stage-0 base for r=1 tap
        for (int c = 0; c < Cv; ++c) {
            if (c + 1 < Cv) cp_wait<1>();
            else            cp_wait<0>();
            __syncthreads();
            if (c + 2 < Cv) { load_stage(ld); cp_commit(); }

            const int so = st * 2 * TSZ;
            const float* a = t0 + so;
            const float* bb = t1 + so;
            float s;
            s = fmaf(w4[0][0], a[0],
                fmaf(w4[0][1], a[1],
                fmaf(w4[0][2], a[TCOLS],
                     w4[0][3] * a[TCOLS + 1])));
            s = fmaf(w4[1][0], bb[0],
                fmaf(w4[1][1], bb[1],
                fmaf(w4[1][2], bb[TCOLS],
                fmaf(w4[1][3], bb[TCOLS + 1], s))));
            *ob = s;
            ob += HW;
            st = (st == NSTAGE - 1) ? 0 : st + 1;
            ld = (ld == NSTAGE - 1) ? 0 : ld + 1;
        }
    } else {
        for (int c = 0; c < Cv; ++c) {
            if (c + 1 < Cv) cp_wait<1>();
            else            cp_wait<0>();
            __syncthreads();
            if (c + 2 < Cv) { load_stage(ld); cp_commit(); }

            const float* tbase = smem + st * 2 * TSZ;
            float s = 0.0f;
#pragma unroll
            for (int r = 0; r < Rv; ++r) {
                const int d = idesc[r];
                float t0v, t1v, b0v, b1v;
                if (d < 0x40000000) {
                    const float* tb = tbase + r * TSZ + d;
                    t0v = tb[0];      t1v = tb[1];
                    b0v = tb[TCOLS];  b1v = tb[TCOLS + 1];
                } else {
                    const int gT = d & 0x1FFFF;
                    const int dv = (d >> 20) & 1;
                    const int gB = gT + ((d >> 21) & 1) * Wv;
                    const float* pc = (r ? pb1 : pb0) + (size_t)c * HW;
                    t0v = __ldg(pc + gT);  t1v = __ldg(pc + gT + dv);
                    b0v = __ldg(pc + gB);  b1v = __ldg(pc + gB + dv);
                }
                s = fmaf(w4[r][0], t0v,
                    fmaf(w4[r][1], t1v,
                    fmaf(w4[r][2], b0v,
                    fmaf(w4[r][3], b1v, s))));
            }
            *ob = s;
            ob += HW;
            st = (st == NSTAGE - 1) ? 0 : st + 1;
            ld = (ld == NSTAGE - 1) ? 0 : ld + 1;
        }
    }
}

extern "C" void kernel_launch(void* const* d_in, const int* in_sizes, int n_in,
                              void* d_out, int out_size)
{
    const float* pred = (const float*)d_in[0];
    const float* mv   = (const float*)d_in[1];
    const float* wgt  = (const float*)d_in[2];
    float* out        = (float*)d_out;

    cudaFuncSetAttribute(mc_warp_kernel,
                         cudaFuncAttributeMaxDynamicSharedMemorySize, SMEM_BYTES);

    dim3 grid(Wv / 32, Hv / TILE_H, Bv);   // 16 x 32 x 4 = 2048 blocks
    mc_warp_kernel<<<grid, 256, SMEM_BYTES>>>(pred, mv, wgt, out);
}